// round 7
// baseline (speedup 1.0000x reference)
#include <cuda_runtime.h>
#include <cuda_bf16.h>
#include <cstdint>

#define N_NODES 20000
#define E_EDGES 640000
#define P_DIM   12
#define H_DIM   128
#define O_DIM   12
#define DINV_BLOCKS ((N_NODES + 255) / 256)   // 79
#define EDGES_PER_WARP 10                     // 3 lanes per edge, 2 idle lanes

// ---------------- scratch (no dynamic allocation; zero-initialized at load) ----------------
// INVARIANT: g_deg and g_agg are all-zero at entry of every kernel_launch call
// (zeroed at module load, re-zeroed inside each launch after consumption).
__device__ float g_deg [N_NODES];
__device__ float g_dinv[N_NODES];
__device__ float g_xs  [N_NODES * P_DIM];   // dinv[n] * x[n,:]
__device__ float g_agg [N_NODES * P_DIM];   // un-dst-normalized aggregate
__device__ float g_az[H_DIM], g_bz[H_DIM], g_ah[H_DIM], g_bh[H_DIM];  // z-gate pre-halved
__device__ float g_probs[P_DIM];

__device__ __forceinline__ float tanh_fast(float x) {
    float y;
    asm("tanh.approx.f32 %0, %1;" : "=f"(y) : "f"(x));
    return y;
}

// degree-7 odd minimax tanh on [-1,1]  (max err ~2e-5; ~1e-6 for |x|<0.3)
#define T1  0.9999932946f
#define T3 (-0.3332173f)
#define T5  0.1328161f
#define T7 (-0.0450642f)

// ---------------- degree accumulation (g_deg starts at 0; +1 folded into dinv) ----------------
__global__ void k_deg(const int* __restrict__ ei, const float* __restrict__ ew) {
    int t = blockIdx.x * blockDim.x + threadIdx.x;
    int e2 = t * 2;
    if (e2 >= E_EDGES) return;
    int2   d = *(const int2*)  (ei + E_EDGES + e2);
    float2 w = *(const float2*)(ew + e2);
    atomicAdd(&g_deg[d.x], w.x);
    atomicAdd(&g_deg[d.y], w.y);
}

// ---------------- fused: dinv(+deg reset) + xs prescale + softmax + weight-fold ----------------
__global__ void __launch_bounds__(256) k_dinv_prep(
        const float* __restrict__ x,   const float* __restrict__ att,
        const float* __restrict__ cwz, const float* __restrict__ cbz,
        const float* __restrict__ Wz,  const float* __restrict__ lbz,
        const float* __restrict__ cwh, const float* __restrict__ cbh,
        const float* __restrict__ Wh,  const float* __restrict__ lbh) {
    int b = blockIdx.x;
    int tid = threadIdx.x;
    if (b < DINV_BLOCKS) {
        __shared__ float s_dinv[256];
        int n0 = b * 256;
        int n  = n0 + tid;
        float dv = 0.0f;
        if (n < N_NODES) {
            float d = g_deg[n] + 1.0f;       // self-loop weight folded here
            dv = rsqrtf(d);                  // d >= 1 > 0 always
            g_dinv[n] = dv;
            g_deg[n]  = 0.0f;                // reset for next launch (replay-safe)
        }
        s_dinv[tid] = dv;
        __syncthreads();
        int base  = n0 * P_DIM;
        int count = min(256, N_NODES - n0) * P_DIM;
        for (int j = tid; j < count; j += 256) {
            g_xs[base + j] = s_dinv[j / P_DIM] * x[base + j];
        }
        if (b == 0 && tid == 0) {
            float m = -1e30f;
            for (int p = 0; p < P_DIM; p++) m = fmaxf(m, att[p]);
            float ex[P_DIM]; float s = 0.f;
            for (int p = 0; p < P_DIM; p++) { ex[p] = __expf(att[p] - m); s += ex[p]; }
            float inv = 1.0f / s;
            for (int p = 0; p < P_DIM; p++) g_probs[p] = ex[p] * inv;
        }
        return;
    }
    // prep: 256 threads = (k in [0,128)) x (half in {0,1}); each covers 64 h-rows.
    bool zgate = (b == DINV_BLOCKS);
    const float* cw = zgate ? cwz : cwh;
    const float* cb = zgate ? cbz : cbh;
    const float* W  = zgate ? Wz  : Wh;
    const float* lb = zgate ? lbz : lbh;
    float* ga = zgate ? g_az : g_ah;
    float* gb = zgate ? g_bz : g_bh;
    float  sc = zgate ? 0.5f : 1.0f;    // pre-halve z-gate for tanh(z/2) sigmoid form

    int k    = tid & 127;
    int half = tid >> 7;
    float pa = 0.f, pb = 0.f;
#pragma unroll 8
    for (int i = 0; i < 64; i++) {
        int h = half * 64 + i;
        float w = W[h * H_DIM + k];
        pa = fmaf(cw[h], w, pa);
        pb = fmaf(cb[h], w, pb);
    }
    __shared__ float sa[H_DIM], sb[H_DIM];
    if (half == 1) { sa[k] = pa; sb[k] = pb; }
    __syncthreads();
    if (half == 0) {
        ga[k] = sc * (pa + sa[k]);
        gb[k] = sc * (pb + sb[k] + lb[k]);
    }
}

// ---------------- edge scatter: 3 lanes per edge -> min sector count ----------------
__device__ __forceinline__ void red_add_v4(float* addr, float4 v) {
    asm volatile("red.global.add.v4.f32 [%0], {%1, %2, %3, %4};"
                 :: "l"(addr), "f"(v.x), "f"(v.y), "f"(v.z), "f"(v.w)
                 : "memory");
}

__global__ void __launch_bounds__(256) k_edge(const int* __restrict__ ei,
                                              const float* __restrict__ ew) {
    int warp_g = (blockIdx.x * blockDim.x + threadIdx.x) >> 5;
    int lane   = threadIdx.x & 31;
    if (lane >= 3 * EDGES_PER_WARP) return;          // 2 idle lanes per warp
    int el = lane / 3;                                // edge-in-warp 0..9
    int j  = lane - el * 3;                           // quarter index 0..2
    int e  = warp_g * EDGES_PER_WARP + el;
    if (e >= E_EDGES) return;
    int   s = __ldg(ei + e);
    int   d = __ldg(ei + E_EDGES + e);
    float w = __ldg(ew + e);
    float4 v = *(const float4*)(g_xs + (size_t)s * P_DIM + 4 * j);
    v.x *= w; v.y *= w; v.z *= w; v.w *= w;
    red_add_v4(g_agg + (size_t)d * P_DIM + 4 * j, v);
}

// ---------------- node kernel: h-tanh on MUFU, z-sigmoid on FMA (pipe split) ----------------
__global__ void __launch_bounds__(256) k_node(const float* __restrict__ wout,
                                              const float* __restrict__ bout,
                                              float* __restrict__ out) {
    __shared__ float s_woutT[O_DIM * H_DIM];
    __shared__ float s_probs[P_DIM], s_bout[O_DIM];

    int tid = threadIdx.x;
    for (int i = tid; i < H_DIM * O_DIM; i += 256) {
        int k = i / O_DIM, o = i % O_DIM;
        s_woutT[o * H_DIM + k] = wout[i];       // transpose -> conflict-free LDS
    }
    if (tid < P_DIM) s_probs[tid] = 0.5f * g_probs[tid];   // fold 0.5 of sigmoid here
    if (tid < O_DIM) s_bout[tid]  = bout[tid];

    int warp = tid >> 5, lane = tid & 31;

    float c_az[4], c_bz[4], c_ah[4], c_bh[4];
#pragma unroll
    for (int j = 0; j < 4; j++) {
        int k = lane + 32 * j;
        c_az[j] = g_az[k];  c_bz[j] = g_bz[k];   // z-gate already pre-halved
        c_ah[j] = g_ah[k];  c_bh[j] = g_bh[k];
    }
    __syncthreads();

    int n = blockIdx.x * 8 + warp;
    if (n >= N_NODES) return;

    float dv = g_dinv[n];
    float4*       ar  = (float4*)(g_agg + (size_t)n * P_DIM);
    const float4* xsr = (const float4*)(g_xs + (size_t)n * P_DIM);
    float a[P_DIM];
#pragma unroll
    for (int j = 0; j < 3; j++) {
        float4 av = ar[j];
        float4 xv = xsr[j];
        a[4*j + 0] = dv * (av.x + xv.x);
        a[4*j + 1] = dv * (av.y + xv.y);
        a[4*j + 2] = dv * (av.z + xv.z);
        a[4*j + 3] = dv * (av.w + xv.w);
    }
    // reset agg row for next launch (after all lanes have loaded it)
    if (lane < 3) ar[lane] = make_float4(0.f, 0.f, 0.f, 0.f);

    float acc[4] = {0.f, 0.f, 0.f, 0.f};
#pragma unroll
    for (int p = 0; p < P_DIM; p++) {
        float ap = a[p];
        float u  = s_probs[p];                 // 0.5 * softmax weight
#pragma unroll
        for (int j = 0; j < 4; j++) {
            // h-gate: MUFU tanh
            float ht = tanh_fast(fmaf(ap, c_ah[j], c_bh[j]));
            // z-gate: (1 - sigmoid(2*zs)) = 0.5*(1 - tanh(zs)), tanh via FMA poly
            float zs = fmaf(ap, c_az[j], c_bz[j]);
            float zc = fminf(fmaxf(zs, -1.0f), 1.0f);     // FMNMX (alu pipe)
            float z2 = zc * zc;
            float q  = fmaf(z2, T7, T5);
            q        = fmaf(z2, q, T3);
            q        = fmaf(z2, q, T1);
            float tz = zc * q;                             // ~tanh(zs)
            float m  = u * ht;                             // 0.5*wp*ht
            float s1 = fmaf(-tz, m, m);                    // m*(1-tz)
            acc[j]  += s1;
        }
    }

    // elu + out matvec (O=12)
    float o_acc[O_DIM];
#pragma unroll
    for (int o = 0; o < O_DIM; o++) o_acc[o] = 0.f;
#pragma unroll
    for (int j = 0; j < 4; j++) {
        float hk = acc[j];
        hk = (hk > 0.f) ? hk : (__expf(hk) - 1.0f);
        int k = lane + 32 * j;
#pragma unroll
        for (int o = 0; o < O_DIM; o++)
            o_acc[o] = fmaf(hk, s_woutT[o * H_DIM + k], o_acc[o]);
    }
#pragma unroll
    for (int off = 16; off > 0; off >>= 1) {
#pragma unroll
        for (int o = 0; o < O_DIM; o++)
            o_acc[o] += __shfl_xor_sync(0xffffffffu, o_acc[o], off);
    }
    if (lane == 0) {
        float* op = out + (size_t)n * O_DIM;
#pragma unroll
        for (int o = 0; o < O_DIM; o++) op[o] = o_acc[o] + s_bout[o];
    }
}

// ---------------- launch ----------------
extern "C" void kernel_launch(void* const* d_in, const int* in_sizes, int n_in,
                              void* d_out, int out_size) {
    const float* x    = (const float*)d_in[0];
    const int*   ei   = (const int*)  d_in[1];
    const float* ew   = (const float*)d_in[2];
    const float* att  = (const float*)d_in[3];
    const float* cwz  = (const float*)d_in[4];
    const float* cbz  = (const float*)d_in[5];
    const float* Wz   = (const float*)d_in[6];
    const float* lbz  = (const float*)d_in[7];
    // r-gate inputs (d_in[8..11]) are mathematically dead: H=0 => R unused
    const float* cwh  = (const float*)d_in[12];
    const float* cbh  = (const float*)d_in[13];
    const float* Wh   = (const float*)d_in[14];
    const float* lbh  = (const float*)d_in[15];
    const float* wout = (const float*)d_in[16];
    const float* bout = (const float*)d_in[17];
    float* out = (float*)d_out;

    k_deg <<<(E_EDGES / 2 + 255) / 256, 256>>>(ei, ew);
    k_dinv_prep<<<DINV_BLOCKS + 2, 256>>>(x, att, cwz, cbz, Wz, lbz,
                                          cwh, cbh, Wh, lbh);
    int edge_warps  = (E_EDGES + EDGES_PER_WARP - 1) / EDGES_PER_WARP;   // 64000
    int edge_blocks = (edge_warps + 7) / 8;                               // 8000
    k_edge<<<edge_blocks, 256>>>(ei, ew);
    k_node<<<N_NODES / 8, 256>>>(wout, bout, out);
}

// round 8
// speedup vs baseline: 1.0453x; 1.0453x over previous
#include <cuda_runtime.h>
#include <cuda_bf16.h>
#include <cuda_fp16.h>
#include <cstdint>

#define N_NODES 20000
#define E_EDGES 640000
#define P_DIM   12
#define H_DIM   128
#define O_DIM   12
#define DINV_BLOCKS ((N_NODES + 255) / 256)   // 79
#define EDGES_PER_WARP 10                     // 3 lanes per edge, 2 idle lanes

// ---------------- scratch (no dynamic allocation; zero-initialized at load) ----------------
// INVARIANT: g_deg and g_agg are all-zero at entry of every kernel_launch call
// (zeroed at module load, re-zeroed inside each launch after consumption).
__device__ float g_deg [N_NODES];
__device__ float g_dinv[N_NODES];
__device__ float g_xs  [N_NODES * P_DIM];   // dinv[n] * x[n,:]
__device__ float g_agg [N_NODES * P_DIM];   // un-dst-normalized aggregate
__device__ float g_az[H_DIM], g_bz[H_DIM], g_ah[H_DIM], g_bh[H_DIM];  // z-gate pre-halved
__device__ float g_probs[P_DIM];

__device__ __forceinline__ __half2 htanh2_fast(__half2 x) {
    __half2 y;
    asm("tanh.approx.f16x2 %0, %1;"
        : "=r"(*(uint32_t*)&y) : "r"(*(const uint32_t*)&x));
    return y;
}

// ---------------- degree accumulation (g_deg starts at 0; +1 folded into dinv) ----------------
__global__ void k_deg(const int* __restrict__ ei, const float* __restrict__ ew) {
    int t = blockIdx.x * blockDim.x + threadIdx.x;
    int e2 = t * 2;
    if (e2 >= E_EDGES) return;
    int2   d = *(const int2*)  (ei + E_EDGES + e2);
    float2 w = *(const float2*)(ew + e2);
    atomicAdd(&g_deg[d.x], w.x);
    atomicAdd(&g_deg[d.y], w.y);
}

// ---------------- fused: dinv(+deg reset) + xs prescale + softmax + weight-fold ----------------
__global__ void __launch_bounds__(256) k_dinv_prep(
        const float* __restrict__ x,   const float* __restrict__ att,
        const float* __restrict__ cwz, const float* __restrict__ cbz,
        const float* __restrict__ Wz,  const float* __restrict__ lbz,
        const float* __restrict__ cwh, const float* __restrict__ cbh,
        const float* __restrict__ Wh,  const float* __restrict__ lbh) {
    int b = blockIdx.x;
    int tid = threadIdx.x;
    if (b < DINV_BLOCKS) {
        __shared__ float s_dinv[256];
        int n0 = b * 256;
        int n  = n0 + tid;
        float dv = 0.0f;
        if (n < N_NODES) {
            float d = g_deg[n] + 1.0f;       // self-loop weight folded here
            dv = rsqrtf(d);                  // d >= 1 > 0 always
            g_dinv[n] = dv;
            g_deg[n]  = 0.0f;                // reset for next launch (replay-safe)
        }
        s_dinv[tid] = dv;
        __syncthreads();
        int base  = n0 * P_DIM;
        int count = min(256, N_NODES - n0) * P_DIM;
        for (int j = tid; j < count; j += 256) {
            g_xs[base + j] = s_dinv[j / P_DIM] * x[base + j];
        }
        if (b == 0 && tid == 0) {
            float m = -1e30f;
            for (int p = 0; p < P_DIM; p++) m = fmaxf(m, att[p]);
            float ex[P_DIM]; float s = 0.f;
            for (int p = 0; p < P_DIM; p++) { ex[p] = __expf(att[p] - m); s += ex[p]; }
            float inv = 1.0f / s;
            for (int p = 0; p < P_DIM; p++) g_probs[p] = ex[p] * inv;
        }
        return;
    }
    // prep: 256 threads = (k in [0,128)) x (half in {0,1}); each covers 64 h-rows.
    bool zgate = (b == DINV_BLOCKS);
    const float* cw = zgate ? cwz : cwh;
    const float* cb = zgate ? cbz : cbh;
    const float* W  = zgate ? Wz  : Wh;
    const float* lb = zgate ? lbz : lbh;
    float* ga = zgate ? g_az : g_ah;
    float* gb = zgate ? g_bz : g_bh;
    float  sc = zgate ? 0.5f : 1.0f;    // pre-halve z-gate for tanh(z/2) sigmoid form

    int k    = tid & 127;
    int half = tid >> 7;
    float pa = 0.f, pb = 0.f;
#pragma unroll 8
    for (int i = 0; i < 64; i++) {
        int h = half * 64 + i;
        float w = W[h * H_DIM + k];
        pa = fmaf(cw[h], w, pa);
        pb = fmaf(cb[h], w, pb);
    }
    __shared__ float sa[H_DIM], sb[H_DIM];
    if (half == 1) { sa[k] = pa; sb[k] = pb; }
    __syncthreads();
    if (half == 0) {
        ga[k] = sc * (pa + sa[k]);
        gb[k] = sc * (pb + sb[k] + lb[k]);
    }
}

// ---------------- edge scatter: 3 lanes per edge -> min sector count ----------------
__device__ __forceinline__ void red_add_v4(float* addr, float4 v) {
    asm volatile("red.global.add.v4.f32 [%0], {%1, %2, %3, %4};"
                 :: "l"(addr), "f"(v.x), "f"(v.y), "f"(v.z), "f"(v.w)
                 : "memory");
}

__global__ void __launch_bounds__(256) k_edge(const int* __restrict__ ei,
                                              const float* __restrict__ ew) {
    int warp_g = (blockIdx.x * blockDim.x + threadIdx.x) >> 5;
    int lane   = threadIdx.x & 31;
    if (lane >= 3 * EDGES_PER_WARP) return;          // 2 idle lanes per warp
    int el = lane / 3;                                // edge-in-warp 0..9
    int j  = lane - el * 3;                           // quarter index 0..2
    int e  = warp_g * EDGES_PER_WARP + el;
    if (e >= E_EDGES) return;
    int   s = __ldg(ei + e);
    int   d = __ldg(ei + E_EDGES + e);
    float w = __ldg(ew + e);
    float4 v = *(const float4*)(g_xs + (size_t)s * P_DIM + 4 * j);
    v.x *= w; v.y *= w; v.z *= w; v.w *= w;
    red_add_v4(g_agg + (size_t)d * P_DIM + 4 * j, v);
}

// ---------------- node kernel: f16x2-packed gates (2 elements per tanh instr) ----------------
__global__ void __launch_bounds__(256) k_node(const float* __restrict__ wout,
                                              const float* __restrict__ bout,
                                              float* __restrict__ out) {
    __shared__ float s_woutT[O_DIM * H_DIM];
    __shared__ float s_probs[P_DIM], s_bout[O_DIM];

    int tid = threadIdx.x;
    for (int i = tid; i < H_DIM * O_DIM; i += 256) {
        int k = i / O_DIM, o = i % O_DIM;
        s_woutT[o * H_DIM + k] = wout[i];       // transpose -> conflict-free LDS
    }
    if (tid < P_DIM) s_probs[tid] = g_probs[tid];
    if (tid < O_DIM) s_bout[tid]  = bout[tid];

    int warp = tid >> 5, lane = tid & 31;

    // pack gate coefficients as half2 pairs: q=0 -> k={lane, lane+32}, q=1 -> k={lane+64, lane+96}
    __half2 cah2[2], cbh2[2], caz2[2], cbz2[2];
#pragma unroll
    for (int q = 0; q < 2; q++) {
        int k0 = lane + 64 * q;
        cah2[q] = __floats2half2_rn(g_ah[k0], g_ah[k0 + 32]);
        cbh2[q] = __floats2half2_rn(g_bh[k0], g_bh[k0 + 32]);
        caz2[q] = __floats2half2_rn(g_az[k0], g_az[k0 + 32]);   // pre-halved
        cbz2[q] = __floats2half2_rn(g_bz[k0], g_bz[k0 + 32]);
    }
    const __half2 h_half  = __floats2half2_rn(0.5f, 0.5f);
    const __half2 h_nhalf = __floats2half2_rn(-0.5f, -0.5f);
    __syncthreads();

    int n = blockIdx.x * 8 + warp;
    if (n >= N_NODES) return;

    float dv = g_dinv[n];
    float4*       ar  = (float4*)(g_agg + (size_t)n * P_DIM);
    const float4* xsr = (const float4*)(g_xs + (size_t)n * P_DIM);
    float a[P_DIM];
#pragma unroll
    for (int j = 0; j < 3; j++) {
        float4 av = ar[j];
        float4 xv = xsr[j];
        a[4*j + 0] = dv * (av.x + xv.x);
        a[4*j + 1] = dv * (av.y + xv.y);
        a[4*j + 2] = dv * (av.z + xv.z);
        a[4*j + 3] = dv * (av.w + xv.w);
    }
    // reset agg row for next launch (after all lanes have loaded it)
    if (lane < 3) ar[lane] = make_float4(0.f, 0.f, 0.f, 0.f);

    // acc index mapping: q=0 holds k={lane, lane+32}; q=1 holds k={lane+64, lane+96}
    float acc[4] = {0.f, 0.f, 0.f, 0.f};
#pragma unroll
    for (int p = 0; p < P_DIM; p++) {
        float   ap  = a[p];
        float   wp  = s_probs[p];
        __half2 ap2 = __float2half2_rn(ap);
#pragma unroll
        for (int q = 0; q < 2; q++) {
            __half2 th2  = htanh2_fast(__hfma2(ap2, cah2[q], cbh2[q]));
            __half2 tz2  = htanh2_fast(__hfma2(ap2, caz2[q], cbz2[q]));
            __half2 omz2 = __hfma2(tz2, h_nhalf, h_half);       // 0.5 - 0.5*tanh(z)
            __half2 g2   = __hmul2(omz2, th2);
            float2  g    = __half22float2(g2);
            acc[2*q + 0] = fmaf(wp, g.x, acc[2*q + 0]);
            acc[2*q + 1] = fmaf(wp, g.y, acc[2*q + 1]);
        }
    }

    // elu + out matvec (O=12); k mapping per acc slot
    float o_acc[O_DIM];
#pragma unroll
    for (int o = 0; o < O_DIM; o++) o_acc[o] = 0.f;
#pragma unroll
    for (int j = 0; j < 4; j++) {
        float hk = acc[j];
        hk = (hk > 0.f) ? hk : (__expf(hk) - 1.0f);
        int k = lane + 32 * ((j & 1) + 2 * (j >> 1));   // j:0->k+0,1->k+32,2->k+64,3->k+96
        (void)k;
        int kk = lane + 32 * j;  // same mapping: {0->0,1->32,2->64,3->96}
#pragma unroll
        for (int o = 0; o < O_DIM; o++)
            o_acc[o] = fmaf(hk, s_woutT[o * H_DIM + kk], o_acc[o]);
    }
#pragma unroll
    for (int off = 16; off > 0; off >>= 1) {
#pragma unroll
        for (int o = 0; o < O_DIM; o++)
            o_acc[o] += __shfl_xor_sync(0xffffffffu, o_acc[o], off);
    }
    if (lane == 0) {
        float* op = out + (size_t)n * O_DIM;
#pragma unroll
        for (int o = 0; o < O_DIM; o++) op[o] = o_acc[o] + s_bout[o];
    }
}

// ---------------- launch ----------------
extern "C" void kernel_launch(void* const* d_in, const int* in_sizes, int n_in,
                              void* d_out, int out_size) {
    const float* x    = (const float*)d_in[0];
    const int*   ei   = (const int*)  d_in[1];
    const float* ew   = (const float*)d_in[2];
    const float* att  = (const float*)d_in[3];
    const float* cwz  = (const float*)d_in[4];
    const float* cbz  = (const float*)d_in[5];
    const float* Wz   = (const float*)d_in[6];
    const float* lbz  = (const float*)d_in[7];
    // r-gate inputs (d_in[8..11]) are mathematically dead: H=0 => R unused
    const float* cwh  = (const float*)d_in[12];
    const float* cbh  = (const float*)d_in[13];
    const float* Wh   = (const float*)d_in[14];
    const float* lbh  = (const float*)d_in[15];
    const float* wout = (const float*)d_in[16];
    const float* bout = (const float*)d_in[17];
    float* out = (float*)d_out;

    k_deg <<<(E_EDGES / 2 + 255) / 256, 256>>>(ei, ew);
    k_dinv_prep<<<DINV_BLOCKS + 2, 256>>>(x, att, cwz, cbz, Wz, lbz,
                                          cwh, cbh, Wh, lbh);
    int edge_warps  = (E_EDGES + EDGES_PER_WARP - 1) / EDGES_PER_WARP;   // 64000
    int edge_blocks = (edge_warps + 7) / 8;                               // 8000
    k_edge<<<edge_blocks, 256>>>(ei, ew);
    k_node<<<N_NODES / 8, 256>>>(wout, bout, out);
}

// round 9
// speedup vs baseline: 1.0860x; 1.0390x over previous
#include <cuda_runtime.h>
#include <cuda_bf16.h>
#include <cstdint>

#define N_NODES 20000
#define E_EDGES 640000
#define P_DIM   12
#define H_DIM   128
#define O_DIM   12
#define DEG_BLOCKS  ((E_EDGES / 2 + 255) / 256)   // 1250
#define DINV_BLOCKS ((N_NODES + 255) / 256)       // 79
#define EDGES_PER_WARP 10                          // 3 lanes per edge, 2 idle lanes

// ---------------- scratch (no dynamic allocation; zero-initialized at load) ----------------
// INVARIANT: g_deg and g_agg are all-zero at entry of every kernel_launch call
// (zeroed at module load, re-zeroed inside each launch after consumption).
__device__ float g_deg [N_NODES];
__device__ float g_dinv[N_NODES];
__device__ float g_xs  [N_NODES * P_DIM];   // dinv[n] * x[n,:]
__device__ float g_agg [N_NODES * P_DIM];   // un-dst-normalized aggregate
__device__ float g_az[H_DIM], g_bz[H_DIM], g_ah[H_DIM], g_bh[H_DIM];  // z-gate pre-halved
__device__ float g_probs[P_DIM];

__device__ __forceinline__ float tanh_fast(float x) {
    float y;
    asm("tanh.approx.f32 %0, %1;" : "=f"(y) : "f"(x));
    return y;
}

// ---------------- deg atomics + weight-fold (independent work, merged grid) ----------------
// blocks [0, DEG_BLOCKS)    : degree accumulation (2 edges/thread)
// block DEG_BLOCKS          : fold z-gate  (az, bz)  [scaled 0.5 for tanh-sigmoid form]
// block DEG_BLOCKS + 1      : fold h-gate  (ah, bh)
__global__ void __launch_bounds__(256) k_deg_fold(
        const int* __restrict__ ei,    const float* __restrict__ ew,
        const float* __restrict__ cwz, const float* __restrict__ cbz,
        const float* __restrict__ Wz,  const float* __restrict__ lbz,
        const float* __restrict__ cwh, const float* __restrict__ cbh,
        const float* __restrict__ Wh,  const float* __restrict__ lbh) {
    int b = blockIdx.x;
    int tid = threadIdx.x;
    if (b < DEG_BLOCKS) {
        int e2 = (b * 256 + tid) * 2;
        if (e2 >= E_EDGES) return;
        int2   d = *(const int2*)  (ei + E_EDGES + e2);
        float2 w = *(const float2*)(ew + e2);
        atomicAdd(&g_deg[d.x], w.x);
        atomicAdd(&g_deg[d.y], w.y);
        return;
    }
    // fold: 256 threads = (k in [0,128)) x (half in {0,1}); each covers 64 h-rows.
    bool zgate = (b == DEG_BLOCKS);
    const float* cw = zgate ? cwz : cwh;
    const float* cb = zgate ? cbz : cbh;
    const float* W  = zgate ? Wz  : Wh;
    const float* lb = zgate ? lbz : lbh;
    float* ga = zgate ? g_az : g_ah;
    float* gb = zgate ? g_bz : g_bh;
    float  sc = zgate ? 0.5f : 1.0f;    // pre-halve z-gate for tanh(z/2) sigmoid form

    int k    = tid & 127;
    int half = tid >> 7;
    float pa = 0.f, pb = 0.f;
#pragma unroll 8
    for (int i = 0; i < 64; i++) {
        int h = half * 64 + i;
        float w = W[h * H_DIM + k];
        pa = fmaf(cw[h], w, pa);
        pb = fmaf(cb[h], w, pb);
    }
    __shared__ float sa[H_DIM], sb[H_DIM];
    if (half == 1) { sa[k] = pa; sb[k] = pb; }
    __syncthreads();
    if (half == 0) {
        ga[k] = sc * (pa + sa[k]);
        gb[k] = sc * (pb + sb[k] + lb[k]);
    }
}

// ---------------- dinv(+deg reset) + xs prescale + softmax ----------------
__global__ void __launch_bounds__(256) k_dinv(const float* __restrict__ x,
                                              const float* __restrict__ att) {
    __shared__ float s_dinv[256];
    int tid = threadIdx.x;
    int n0 = blockIdx.x * 256;
    int n  = n0 + tid;
    float dv = 0.0f;
    if (n < N_NODES) {
        float d = g_deg[n] + 1.0f;       // self-loop weight folded here
        dv = rsqrtf(d);                  // d >= 1 > 0 always
        g_dinv[n] = dv;
        g_deg[n]  = 0.0f;                // reset for next launch (replay-safe)
    }
    s_dinv[tid] = dv;
    __syncthreads();
    int base  = n0 * P_DIM;
    int count = min(256, N_NODES - n0) * P_DIM;
    for (int j = tid; j < count; j += 256) {
        g_xs[base + j] = s_dinv[j / P_DIM] * x[base + j];
    }
    if (blockIdx.x == 0 && tid == 0) {
        float m = -1e30f;
        for (int p = 0; p < P_DIM; p++) m = fmaxf(m, att[p]);
        float ex[P_DIM]; float s = 0.f;
        for (int p = 0; p < P_DIM; p++) { ex[p] = __expf(att[p] - m); s += ex[p]; }
        float inv = 1.0f / s;
        for (int p = 0; p < P_DIM; p++) g_probs[p] = ex[p] * inv;
    }
}

// ---------------- edge scatter: 3 lanes per edge -> min sector count ----------------
__device__ __forceinline__ void red_add_v4(float* addr, float4 v) {
    asm volatile("red.global.add.v4.f32 [%0], {%1, %2, %3, %4};"
                 :: "l"(addr), "f"(v.x), "f"(v.y), "f"(v.z), "f"(v.w)
                 : "memory");
}

__global__ void __launch_bounds__(256) k_edge(const int* __restrict__ ei,
                                              const float* __restrict__ ew) {
    int warp_g = (blockIdx.x * blockDim.x + threadIdx.x) >> 5;
    int lane   = threadIdx.x & 31;
    if (lane >= 3 * EDGES_PER_WARP) return;          // 2 idle lanes per warp
    int el = lane / 3;                                // edge-in-warp 0..9
    int j  = lane - el * 3;                           // quarter index 0..2
    int e  = warp_g * EDGES_PER_WARP + el;
    if (e >= E_EDGES) return;
    int   s = __ldg(ei + e);
    int   d = __ldg(ei + E_EDGES + e);
    float w = __ldg(ew + e);
    float4 v = *(const float4*)(g_xs + (size_t)s * P_DIM + 4 * j);
    v.x *= w; v.y *= w; v.z *= w; v.w *= w;
    red_add_v4(g_agg + (size_t)d * P_DIM + 4 * j, v);
}

// ---------------- node kernel: f32 tanh gates + 18-SHFL split reduction ----------------
__global__ void __launch_bounds__(256) k_node(const float* __restrict__ wout,
                                              const float* __restrict__ bout,
                                              float* __restrict__ out) {
    __shared__ float s_woutT[O_DIM * H_DIM];
    __shared__ float s_probs[P_DIM], s_bout[O_DIM];

    int tid = threadIdx.x;
    for (int i = tid; i < H_DIM * O_DIM; i += 256) {
        int k = i / O_DIM, o = i % O_DIM;
        s_woutT[o * H_DIM + k] = wout[i];       // transpose -> conflict-free LDS
    }
    if (tid < P_DIM) s_probs[tid] = g_probs[tid];
    if (tid < O_DIM) s_bout[tid]  = bout[tid];

    int warp = tid >> 5, lane = tid & 31;

    float c_az[4], c_bz[4], c_ah[4], c_bh[4];
#pragma unroll
    for (int j = 0; j < 4; j++) {
        int k = lane + 32 * j;
        c_az[j] = g_az[k];  c_bz[j] = g_bz[k];   // z-gate already pre-halved
        c_ah[j] = g_ah[k];  c_bh[j] = g_bh[k];
    }
    __syncthreads();

    int n = blockIdx.x * 8 + warp;
    if (n >= N_NODES) return;

    float dv = g_dinv[n];
    float4*       ar  = (float4*)(g_agg + (size_t)n * P_DIM);
    const float4* xsr = (const float4*)(g_xs + (size_t)n * P_DIM);
    float a[P_DIM];
#pragma unroll
    for (int j = 0; j < 3; j++) {
        float4 av = ar[j];
        float4 xv = xsr[j];
        a[4*j + 0] = dv * (av.x + xv.x);
        a[4*j + 1] = dv * (av.y + xv.y);
        a[4*j + 2] = dv * (av.z + xv.z);
        a[4*j + 3] = dv * (av.w + xv.w);
    }
    // reset agg row for next launch (after all lanes have loaded it)
    if (lane < 3) ar[lane] = make_float4(0.f, 0.f, 0.f, 0.f);

    float acc[4] = {0.f, 0.f, 0.f, 0.f};
#pragma unroll
    for (int p = 0; p < P_DIM; p++) {
        float ap = a[p];
        float wp = s_probs[p];
#pragma unroll
        for (int j = 0; j < 4; j++) {
            // (1 - sigmoid(2*zs')) = 0.5 - 0.5*tanh(zs')   (coeffs pre-halved)
            float zs  = fmaf(ap, c_az[j], c_bz[j]);
            float omz = fmaf(-0.5f, tanh_fast(zs), 0.5f);
            float ht  = tanh_fast(fmaf(ap, c_ah[j], c_bh[j]));
            acc[j] = fmaf(wp * omz, ht, acc[j]);
        }
    }

    // elu + out matvec (O=12)
    float o_acc[O_DIM];
#pragma unroll
    for (int o = 0; o < O_DIM; o++) o_acc[o] = 0.f;
#pragma unroll
    for (int j = 0; j < 4; j++) {
        float hk = acc[j];
        hk = (hk > 0.f) ? hk : (__expf(hk) - 1.0f);
        int k = lane + 32 * j;
#pragma unroll
        for (int o = 0; o < O_DIM; o++)
            o_acc[o] = fmaf(hk, s_woutT[o * H_DIM + k], o_acc[o]);
    }

    // split-ownership butterfly: 18 SHFLs instead of 60.
    // Round A (xor 16): 12 -> 6 values/lane.  lane<16 owns o=t, lane>=16 owns o=t+6.
    float v6[6];
    bool lo16 = (lane & 16) == 0;
#pragma unroll
    for (int t = 0; t < 6; t++) {
        float send = lo16 ? o_acc[t + 6] : o_acc[t];
        float recv = __shfl_xor_sync(0xffffffffu, send, 16);
        v6[t] = (lo16 ? o_acc[t] : o_acc[t + 6]) + recv;
    }
    // Round B (xor 8): 6 -> 3 values/lane.  o = t + 3*(lane>>3).
    float v3[3];
    bool lo8 = (lane & 8) == 0;
#pragma unroll
    for (int t = 0; t < 3; t++) {
        float send = lo8 ? v6[t + 3] : v6[t];
        float recv = __shfl_xor_sync(0xffffffffu, send, 8);
        v3[t] = (lo8 ? v6[t] : v6[t + 3]) + recv;
    }
    // Rounds C-E (xor 4,2,1): plain butterfly on 3 values.
#pragma unroll
    for (int off = 4; off > 0; off >>= 1) {
#pragma unroll
        for (int t = 0; t < 3; t++)
            v3[t] += __shfl_xor_sync(0xffffffffu, v3[t], off);
    }
    // write: group g = lane>>3 owns o = 3g + t; lanes r=lane&7 < 3 emit one value each.
    int r = lane & 7;
    if (r < 3) {
        int o = 3 * (lane >> 3) + r;
        out[(size_t)n * O_DIM + o] = v3[r] + s_bout[o];
    }
}

// ---------------- launch ----------------
extern "C" void kernel_launch(void* const* d_in, const int* in_sizes, int n_in,
                              void* d_out, int out_size) {
    const float* x    = (const float*)d_in[0];
    const int*   ei   = (const int*)  d_in[1];
    const float* ew   = (const float*)d_in[2];
    const float* att  = (const float*)d_in[3];
    const float* cwz  = (const float*)d_in[4];
    const float* cbz  = (const float*)d_in[5];
    const float* Wz   = (const float*)d_in[6];
    const float* lbz  = (const float*)d_in[7];
    // r-gate inputs (d_in[8..11]) are mathematically dead: H=0 => R unused
    const float* cwh  = (const float*)d_in[12];
    const float* cbh  = (const float*)d_in[13];
    const float* Wh   = (const float*)d_in[14];
    const float* lbh  = (const float*)d_in[15];
    const float* wout = (const float*)d_in[16];
    const float* bout = (const float*)d_in[17];
    float* out = (float*)d_out;

    k_deg_fold<<<DEG_BLOCKS + 2, 256>>>(ei, ew, cwz, cbz, Wz, lbz,
                                        cwh, cbh, Wh, lbh);
    k_dinv<<<DINV_BLOCKS, 256>>>(x, att);
    int edge_warps  = (E_EDGES + EDGES_PER_WARP - 1) / EDGES_PER_WARP;   // 64000
    int edge_blocks = (edge_warps + 7) / 8;                               // 8000
    k_edge<<<edge_blocks, 256>>>(ei, ew);
    k_node<<<N_NODES / 8, 256>>>(wout, bout, out);
}